// round 1
// baseline (speedup 1.0000x reference)
#include <cuda_runtime.h>
#include <cuda_bf16.h>

// ---------------------------------------------------------------------------
// BasicConvolutionBlock: sparse 3D conv (gather-GEMM, K=27, Cin=Cout=64)
//                        + BatchNorm (batch stats) + ReLU
// Inputs (metadata order):
//   d_in[0] feats  [N,64]   f32
//   d_in[1] W      [27,64,64] f32
//   d_in[2] gamma  [64]     f32
//   d_in[3] beta   [64]     f32
//   d_in[4] nbr_idx[27,N]   i32
//   d_in[5] mask   [27,N]   i32
// Output: [N,64] f32
// ---------------------------------------------------------------------------

#define CIN  64
#define COUT 64
#define TILE_ROWS 128
#define CTA_THREADS 256
#define BN_EPS 1e-5f

// Global scratch for BN statistics: [0:64) = sum, [64:128) = sumsq
__device__ float g_stats[128];

__global__ void zero_stats_kernel() {
    int t = threadIdx.x;
    if (t < 128) g_stats[t] = 0.0f;
}

// ---- packed f32x2 helpers (Blackwell; ptxas will not auto-fuse these) ------
__device__ __forceinline__ void ffma2(unsigned long long& d,
                                      unsigned long long a,
                                      unsigned long long b) {
#if __CUDA_ARCH__ >= 1000
    asm("fma.rn.f32x2 %0, %1, %2, %0;" : "+l"(d) : "l"(a), "l"(b));
#else
    float2* df = reinterpret_cast<float2*>(&d);
    const float2* af = reinterpret_cast<const float2*>(&a);
    const float2* bf = reinterpret_cast<const float2*>(&b);
    df->x = fmaf(af->x, bf->x, df->x);
    df->y = fmaf(af->y, bf->y, df->y);
#endif
}

__device__ __forceinline__ unsigned long long pack2(float x) {
    unsigned long long r;
    asm("mov.b64 %0, {%1, %1};" : "=l"(r) : "f"(x));
    return r;
}

__device__ __forceinline__ float2 u2f(unsigned long long u) {
    float2 f;
    asm("mov.b64 {%0, %1}, %2;" : "=f"(f.x), "=f"(f.y) : "l"(u));
    return f;
}

// XOR swizzle for the gathered tile: g[row][f4] (f4 = float4 column 0..15)
// Guarantees conflict-free LDS.128 for both the gather stores (2 thr/row,
// half-based) and the GEMM reads (4 consecutive rows per warp sub-tile).
__device__ __forceinline__ int gswz(int row, int f4) {
    return (row << 6) + (((f4 ^ (row & 3)) ^ ((f4 >> 1) & 4)) << 2);
}

// ---------------------------------------------------------------------------
// Conv kernel. CTA = 256 threads handles 128 rows.
// Thread (tx,ty): tx = tid&7 owns channels {tx*4 .. tx*4+3} and {32+tx*4 ..},
//                 ty = tid>>3 owns rows {ty, ty+32, ty+64, ty+96}.
// Accumulates over all K offsets in registers (4 rows x 8 ch as 16 f32x2).
// ---------------------------------------------------------------------------
__global__ void __launch_bounds__(CTA_THREADS, 2)
conv_kernel(const float* __restrict__ feats,
            const float* __restrict__ Wg,
            const int*   __restrict__ nbr,
            const int*   __restrict__ mask,
            float*       __restrict__ out,
            int n, int kk) {
    __shared__ float gbuf[TILE_ROWS * CIN];   // 32 KB (swizzled)
    __shared__ float Ws[CIN * COUT];          // 16 KB

    const int tid = threadIdx.x;
    const int tx = tid & 7;
    const int ty = tid >> 3;
    const int base = blockIdx.x * TILE_ROWS;

    unsigned long long acc[4][4];
#pragma unroll
    for (int r = 0; r < 4; ++r)
#pragma unroll
        for (int j = 0; j < 4; ++j) acc[r][j] = 0ull;

    const int grow_g = base + (tid >> 1);   // gather row for this thread
    const int ghalf  = tid & 1;             // which 8 float4s of the row

    for (int k = 0; k < kk; ++k) {
        __syncthreads();  // previous compute done before smem overwrite

        // --- stage W[k] (64x64) ---
        {
            const float4* wsrc = (const float4*)(Wg + (size_t)k * CIN * COUT);
            float4* wdst = (float4*)Ws;
#pragma unroll
            for (int j = 0; j < 4; ++j)
                wdst[tid + j * CTA_THREADS] = wsrc[tid + j * CTA_THREADS];
        }

        // --- mask-aware gather of 128 rows into swizzled smem ---
        {
            const int kbase = k * n;
            const float4* src = nullptr;
            if (grow_g < n && mask[kbase + grow_g] != 0) {
                int s = nbr[kbase + grow_g];
                src = (const float4*)(feats + (size_t)s * CIN) + ghalf * 8;
            }
            const int row = tid >> 1;
#pragma unroll
            for (int j = 0; j < 8; ++j) {
                float4 v = src ? src[j] : make_float4(0.f, 0.f, 0.f, 0.f);
                *(float4*)&gbuf[gswz(row, ghalf * 8 + j)] = v;
            }
        }

        __syncthreads();

        // --- register-blocked GEMM: acc += g_tile @ W[k] ---
        for (int i = 0; i < CIN; i += 4) {
            ulonglong2 w0[4], w1[4];
#pragma unroll
            for (int ii = 0; ii < 4; ++ii) {
                const float* wp = &Ws[(i + ii) * COUT + tx * 4];
                w0[ii] = *(const ulonglong2*)wp;
                w1[ii] = *(const ulonglong2*)(wp + 32);
            }
#pragma unroll
            for (int rr = 0; rr < 4; ++rr) {
                const int row = ty + rr * 32;
                float4 gv = *(const float4*)&gbuf[gswz(row, i >> 2)];
                float gs0 = gv.x, gs1 = gv.y, gs2 = gv.z, gs3 = gv.w;
                unsigned long long gp;
                gp = pack2(gs0);
                ffma2(acc[rr][0], gp, w0[0].x);
                ffma2(acc[rr][1], gp, w0[0].y);
                ffma2(acc[rr][2], gp, w1[0].x);
                ffma2(acc[rr][3], gp, w1[0].y);
                gp = pack2(gs1);
                ffma2(acc[rr][0], gp, w0[1].x);
                ffma2(acc[rr][1], gp, w0[1].y);
                ffma2(acc[rr][2], gp, w1[1].x);
                ffma2(acc[rr][3], gp, w1[1].y);
                gp = pack2(gs2);
                ffma2(acc[rr][0], gp, w0[2].x);
                ffma2(acc[rr][1], gp, w0[2].y);
                ffma2(acc[rr][2], gp, w1[2].x);
                ffma2(acc[rr][3], gp, w1[2].y);
                gp = pack2(gs3);
                ffma2(acc[rr][0], gp, w0[3].x);
                ffma2(acc[rr][1], gp, w0[3].y);
                ffma2(acc[rr][2], gp, w1[3].x);
                ffma2(acc[rr][3], gp, w1[3].y);
            }
        }
    }

    // --- write raw conv to out, accumulate BN partial stats ---
    float s[8], q[8];
#pragma unroll
    for (int j = 0; j < 8; ++j) { s[j] = 0.f; q[j] = 0.f; }

#pragma unroll
    for (int rr = 0; rr < 4; ++rr) {
        const int row = base + ty + rr * 32;
        if (row < n) {
            float2 a0 = u2f(acc[rr][0]);
            float2 a1 = u2f(acc[rr][1]);
            float2 a2 = u2f(acc[rr][2]);
            float2 a3 = u2f(acc[rr][3]);
            float4 v0 = make_float4(a0.x, a0.y, a1.x, a1.y);
            float4 v1 = make_float4(a2.x, a2.y, a3.x, a3.y);
            *(float4*)&out[(size_t)row * COUT + tx * 4]      = v0;
            *(float4*)&out[(size_t)row * COUT + 32 + tx * 4] = v1;
            s[0] += v0.x; q[0] += v0.x * v0.x;
            s[1] += v0.y; q[1] += v0.y * v0.y;
            s[2] += v0.z; q[2] += v0.z * v0.z;
            s[3] += v0.w; q[3] += v0.w * v0.w;
            s[4] += v1.x; q[4] += v1.x * v1.x;
            s[5] += v1.y; q[5] += v1.y * v1.y;
            s[6] += v1.z; q[6] += v1.z * v1.z;
            s[7] += v1.w; q[7] += v1.w * v1.w;
        }
    }

    // warp reduce over the 4 ty values sharing each channel (lane bits 3,4)
#pragma unroll
    for (int j = 0; j < 8; ++j) {
        s[j] += __shfl_xor_sync(0xffffffffu, s[j], 8);
        s[j] += __shfl_xor_sync(0xffffffffu, s[j], 16);
        q[j] += __shfl_xor_sync(0xffffffffu, q[j], 8);
        q[j] += __shfl_xor_sync(0xffffffffu, q[j], 16);
    }
    if ((tid & 31) < 8) {
#pragma unroll
        for (int j = 0; j < 8; ++j) {
            int c = (j < 4) ? (tx * 4 + j) : (32 + tx * 4 + (j - 4));
            atomicAdd(&g_stats[c], s[j]);
            atomicAdd(&g_stats[64 + c], q[j]);
        }
    }
}

// ---------------------------------------------------------------------------
// BN (batch stats) + ReLU, in place on out.
// ---------------------------------------------------------------------------
__global__ void bn_relu_kernel(float* __restrict__ out,
                               const float* __restrict__ gamma,
                               const float* __restrict__ beta,
                               int n) {
    __shared__ float sc[COUT], bi[COUT];
    const int tid = threadIdx.x;
    if (tid < COUT) {
        float inv_n = 1.0f / (float)n;
        float mean = g_stats[tid] * inv_n;
        float var = fmaxf(g_stats[64 + tid] * inv_n - mean * mean, 0.0f);
        float inv = rsqrtf(var + BN_EPS);
        float scl = gamma[tid] * inv;
        sc[tid] = scl;
        bi[tid] = beta[tid] - mean * scl;
    }
    __syncthreads();

    const int total = n * (COUT / 4);
    float4* o4 = (float4*)out;
    for (int i = blockIdx.x * blockDim.x + tid; i < total;
         i += gridDim.x * blockDim.x) {
        float4 v = o4[i];
        int c = (i & 15) << 2;
        v.x = fmaxf(fmaf(v.x, sc[c],     bi[c]),     0.f);
        v.y = fmaxf(fmaf(v.y, sc[c + 1], bi[c + 1]), 0.f);
        v.z = fmaxf(fmaf(v.z, sc[c + 2], bi[c + 2]), 0.f);
        v.w = fmaxf(fmaf(v.w, sc[c + 3], bi[c + 3]), 0.f);
        o4[i] = v;
    }
}

// ---------------------------------------------------------------------------
extern "C" void kernel_launch(void* const* d_in, const int* in_sizes, int n_in,
                              void* d_out, int out_size) {
    const float* feats = (const float*)d_in[0];
    const float* Wg    = (const float*)d_in[1];
    const float* gamma = (const float*)d_in[2];
    const float* beta  = (const float*)d_in[3];
    const int*   nbr   = (const int*)d_in[4];
    const int*   mask  = (const int*)d_in[5];
    float* out = (float*)d_out;

    const int n  = in_sizes[0] / CIN;                 // 200000
    const int kk = in_sizes[1] / (CIN * COUT);        // 27

    zero_stats_kernel<<<1, 128>>>();

    const int grid = (n + TILE_ROWS - 1) / TILE_ROWS;
    conv_kernel<<<grid, CTA_THREADS>>>(feats, Wg, nbr, mask, out, n, kk);

    int bn_grid = (n * (COUT / 4) + 255) / 256;
    if (bn_grid > 1184) bn_grid = 1184;
    bn_relu_kernel<<<bn_grid, 256>>>(out, gamma, beta, n);
}

// round 7
// speedup vs baseline: 2.7001x; 2.7001x over previous
#include <cuda_runtime.h>
#include <cstdint>

// ---------------------------------------------------------------------------
// BasicConvolutionBlock: sparse conv (gather-GEMM, K=27, Cin=Cout=64) + BN + ReLU
// Legacy mma.sync tf32 implementation (compute_100-safe; no tcgen05).
// A operand: raw f32 (HW truncates to tf32). B operand: pre-rounded (rna) W^T.
//   d_in[0] feats [N,64] f32      d_in[1] W [27,64,64] f32
//   d_in[2] gamma [64]            d_in[3] beta [64]
//   d_in[4] nbr_idx [27,N] i32    d_in[5] mask [27,N] i32
// out: [N,64] f32
// ---------------------------------------------------------------------------

#define CIN   64
#define COUT  64
#define MAXK  27
#define M_TILE 128
#define CTA   256
#define BN_EPS 1e-5f

// dynamic smem: A double-buffer (2 x 32KB) + WT double-buffer (2 x 16KB)
#define A_OFF0 0u
#define A_OFF1 32768u
#define B_OFF0 65536u
#define B_OFF1 81920u
#define SMEM_BYTES 98304

__device__ float g_stats[128];              // [0:64) sum, [64:128) sumsq
__device__ float g_wt[MAXK * CIN * COUT];   // tf32-rounded W, transposed [k][cout][cin]

// ---------------- helpers ---------------------------------------------------
__device__ __forceinline__ float to_tf32(float x) {
    uint32_t r;
    asm("cvt.rna.tf32.f32 %0, %1;" : "=r"(r) : "f"(x));   // dst must be .b32
    return __uint_as_float(r);
}

__device__ __forceinline__ uint32_t smem_u32(const void* p) {
    uint32_t a;
    asm("{ .reg .u64 t; cvta.to.shared.u64 t, %1; cvt.u32.u64 %0, t; }"
        : "=r"(a) : "l"(p));
    return a;
}

__device__ __forceinline__ void cpa16(uint32_t dst, const void* src, uint32_t sz) {
    asm volatile("cp.async.cg.shared.global [%0], [%1], 16, %2;"
                 :: "r"(dst), "l"(src), "r"(sz) : "memory");
}
#define CP_COMMIT() asm volatile("cp.async.commit_group;" ::: "memory")
#define CP_WAIT0()  asm volatile("cp.async.wait_group 0;" ::: "memory")

// swizzled float4 index inside a [rows][64-float] tile
__device__ __forceinline__ uint32_t swz4(int r, int q) {
    return (uint32_t)(r * 16 + (q ^ (r & 7)));
}

// ---------------------------------------------------------------------------
__global__ void zero_stats_kernel() {
    int t = threadIdx.x;
    if (t < 128) g_stats[t] = 0.0f;
}

__global__ void prep_w_kernel(const float* __restrict__ w) {
    int k = blockIdx.x;
    const float* ws = w + (size_t)k * CIN * COUT;
    float* wd = g_wt + (size_t)k * CIN * COUT;
    for (int e = threadIdx.x; e < CIN * COUT; e += blockDim.x) {
        int ci = e >> 6, co = e & 63;
        wd[co * 64 + ci] = to_tf32(ws[e]);   // transpose: [cout][cin]
    }
}

// ---------------------------------------------------------------------------
// Conv kernel: CTA = 256 thr (8 warps), tile = 128 rows. Warp w owns rows
// [w*16, w*16+16). Accumulate all 27 offsets in registers via mma.sync tf32.
// ---------------------------------------------------------------------------
__global__ void __launch_bounds__(CTA, 2)
conv_kernel(const float* __restrict__ feats,
            const int* __restrict__ nbr,
            const int* __restrict__ mask,
            float*     __restrict__ out,
            int n, int kk) {
    extern __shared__ char smem[];
    __shared__ float sst[128];
    const uint32_t sb = smem_u32(smem);

    const int tid  = threadIdx.x;
    const int warp = tid >> 5, lane = tid & 31;
    const int lr = lane >> 2, le = lane & 3;
    const int cb = blockIdx.x * M_TILE;

    if (tid < 128) sst[tid] = 0.0f;

    const int rg = tid >> 1;       // gather row (0..127), 2 threads per row
    const int h  = tid & 1;        // which 128B half
    const int grow = cb + rg;

    const uint32_t a_off[2] = {A_OFF0, A_OFF1};
    const uint32_t b_off[2] = {B_OFF0, B_OFF1};

    // --- idx/mask prefetch (depth 2) + stage issue ---------------------------
    int pn; uint32_t pv;
    {
        if (grow < n) { int o = grow; pv = (uint32_t)mask[o]; pn = nbr[o]; }
        else          { pv = 0; pn = 0; }
    }

    // issue stage 0
    {
        const char* src = (const char*)(feats + (size_t)pn * CIN + h * 32);
        uint32_t abase = sb + a_off[0];
        uint32_t sz = pv ? 16u : 0u;
#pragma unroll
        for (int j = 0; j < 8; ++j)
            cpa16(abase + (swz4(rg, h * 8 + j) << 4), src + j * 16, sz);
        const char* wsrc = (const char*)g_wt;
        uint32_t bbase = sb + b_off[0];
#pragma unroll
        for (int j = 0; j < 4; ++j) {
            int e4 = tid + j * CTA;
            cpa16(bbase + (swz4(e4 >> 4, e4 & 15) << 4), wsrc + e4 * 16, 16u);
        }
        CP_COMMIT();
    }

    if (kk > 1) {
        if (grow < n) { int o = n + grow; pv = (uint32_t)mask[o]; pn = nbr[o]; }
        else          { pv = 0; pn = 0; }
    }

    float acc[8][4];
#pragma unroll
    for (int nt = 0; nt < 8; ++nt)
#pragma unroll
        for (int j = 0; j < 4; ++j) acc[nt][j] = 0.0f;

    const int ra = warp * 16 + lr;

    for (int k = 0; k < kk; ++k) {
        CP_WAIT0();
        __syncthreads();

        // issue stage k+1 using prefetched idx/mask
        if (k + 1 < kk) {
            const int buf = (k + 1) & 1;
            const char* src = (const char*)(feats + (size_t)pn * CIN + h * 32);
            uint32_t abase = sb + a_off[buf];
            uint32_t sz = pv ? 16u : 0u;
#pragma unroll
            for (int j = 0; j < 8; ++j)
                cpa16(abase + (swz4(rg, h * 8 + j) << 4), src + j * 16, sz);
            const char* wsrc = (const char*)(g_wt + (size_t)(k + 1) * CIN * COUT);
            uint32_t bbase = sb + b_off[buf];
#pragma unroll
            for (int j = 0; j < 4; ++j) {
                int e4 = tid + j * CTA;
                cpa16(bbase + (swz4(e4 >> 4, e4 & 15) << 4), wsrc + e4 * 16, 16u);
            }
            CP_COMMIT();
        }
        // prefetch idx/mask for stage k+2
        if (k + 2 < kk) {
            if (grow < n) { int o = (k + 2) * n + grow; pv = (uint32_t)mask[o]; pn = nbr[o]; }
            else          { pv = 0; pn = 0; }
        }

        // ---- compute from buffer k&1 ----
        const char* Ap = smem + a_off[k & 1];
        const char* Bp = smem + b_off[k & 1];
#pragma unroll
        for (int ks = 0; ks < 8; ++ks) {
            const uint32_t bq = (uint32_t)((((2 * ks) ^ lr) << 4) + (le << 2));
            const uint32_t a0o = (uint32_t)(ra << 8) + bq;
            uint32_t a0 = *(const uint32_t*)(Ap + a0o);
            uint32_t a1 = *(const uint32_t*)(Ap + a0o + 2048);
            uint32_t a2 = *(const uint32_t*)(Ap + (a0o ^ 16));
            uint32_t a3 = *(const uint32_t*)(Ap + ((a0o + 2048) ^ 16));
#pragma unroll
            for (int nt = 0; nt < 8; ++nt) {
                const uint32_t b0o = (uint32_t)((nt * 8 + lr) << 8) + bq;
                uint32_t b0 = *(const uint32_t*)(Bp + b0o);
                uint32_t b1 = *(const uint32_t*)(Bp + (b0o ^ 16));
                asm volatile(
                    "mma.sync.aligned.m16n8k8.row.col.f32.tf32.tf32.f32 "
                    "{%0,%1,%2,%3}, {%4,%5,%6,%7}, {%8,%9}, {%0,%1,%2,%3};"
                    : "+f"(acc[nt][0]), "+f"(acc[nt][1]),
                      "+f"(acc[nt][2]), "+f"(acc[nt][3])
                    : "r"(a0), "r"(a1), "r"(a2), "r"(a3), "r"(b0), "r"(b1));
            }
        }
    }

    // ---- BN partial stats from register fragments (invalid rows hold 0) ----
#pragma unroll
    for (int nt = 0; nt < 8; ++nt) {
        float s0 = acc[nt][0] + acc[nt][2];
        float q0 = acc[nt][0] * acc[nt][0] + acc[nt][2] * acc[nt][2];
        float s1 = acc[nt][1] + acc[nt][3];
        float q1 = acc[nt][1] * acc[nt][1] + acc[nt][3] * acc[nt][3];
#pragma unroll
        for (int d = 4; d <= 16; d <<= 1) {
            s0 += __shfl_xor_sync(0xffffffffu, s0, d);
            q0 += __shfl_xor_sync(0xffffffffu, q0, d);
            s1 += __shfl_xor_sync(0xffffffffu, s1, d);
            q1 += __shfl_xor_sync(0xffffffffu, q1, d);
        }
        if (lane < 4) {
            int c0 = nt * 8 + lane * 2;
            atomicAdd(&sst[c0], s0);      atomicAdd(&sst[64 + c0], q0);
            atomicAdd(&sst[c0 + 1], s1);  atomicAdd(&sst[64 + c0 + 1], q1);
        }
    }

    // ---- fragments -> smem (swizzled) -> coalesced global write ----
    __syncthreads();
    {
        char* Sp = smem;   // reuse buffer A0
#pragma unroll
        for (int nt = 0; nt < 8; ++nt) {
            int col = nt * 8 + le * 2;
            int q = col >> 2, e = col & 3;
            uint32_t o0 = (swz4(ra, q) << 4) + (uint32_t)(e * 4);
            *(float2*)(Sp + o0)        = make_float2(acc[nt][0], acc[nt][1]);
            *(float2*)(Sp + o0 + 2048) = make_float2(acc[nt][2], acc[nt][3]);
        }
    }
    __syncthreads();
    {
        const char* Sp = smem;
#pragma unroll
        for (int it = 0; it < 8; ++it) {
            int rl = (tid >> 4) + it * 16;
            int q = tid & 15;
            float4 v = *(const float4*)(Sp + (swz4(rl, q) << 4));
            int gr = cb + rl;
            if (gr < n) ((float4*)out)[(size_t)gr * 16 + q] = v;
        }
    }
    if (tid < 128) atomicAdd(&g_stats[tid], sst[tid]);
}

// ---------------------------------------------------------------------------
__global__ void bn_relu_kernel(float* __restrict__ out,
                               const float* __restrict__ gamma,
                               const float* __restrict__ beta,
                               int n) {
    __shared__ float sc[COUT], bi[COUT];
    const int tid = threadIdx.x;
    if (tid < COUT) {
        float inv_n = 1.0f / (float)n;
        float mean = g_stats[tid] * inv_n;
        float var = fmaxf(g_stats[64 + tid] * inv_n - mean * mean, 0.0f);
        float inv = rsqrtf(var + BN_EPS);
        float scl = gamma[tid] * inv;
        sc[tid] = scl;
        bi[tid] = beta[tid] - mean * scl;
    }
    __syncthreads();

    const int total = n * (COUT / 4);
    float4* o4 = (float4*)out;
    for (int i = blockIdx.x * blockDim.x + tid; i < total;
         i += gridDim.x * blockDim.x) {
        float4 v = o4[i];
        int c = (i & 15) << 2;
        v.x = fmaxf(fmaf(v.x, sc[c],     bi[c]),     0.f);
        v.y = fmaxf(fmaf(v.y, sc[c + 1], bi[c + 1]), 0.f);
        v.z = fmaxf(fmaf(v.z, sc[c + 2], bi[c + 2]), 0.f);
        v.w = fmaxf(fmaf(v.w, sc[c + 3], bi[c + 3]), 0.f);
        o4[i] = v;
    }
}

// ---------------------------------------------------------------------------
extern "C" void kernel_launch(void* const* d_in, const int* in_sizes, int n_in,
                              void* d_out, int out_size) {
    const float* feats = (const float*)d_in[0];
    const float* Wg    = (const float*)d_in[1];
    const float* gamma = (const float*)d_in[2];
    const float* beta  = (const float*)d_in[3];
    const int*   nbr   = (const int*)d_in[4];
    const int*   mask  = (const int*)d_in[5];
    float* out = (float*)d_out;

    const int n  = in_sizes[0] / CIN;              // 200000
    const int kk = in_sizes[1] / (CIN * COUT);     // 27

    cudaFuncSetAttribute(conv_kernel,
                         cudaFuncAttributeMaxDynamicSharedMemorySize,
                         SMEM_BYTES);

    zero_stats_kernel<<<1, 128>>>();
    prep_w_kernel<<<kk, 256>>>(Wg);

    const int grid = (n + M_TILE - 1) / M_TILE;    // 1563
    conv_kernel<<<grid, CTA, SMEM_BYTES>>>(feats, nbr, mask, out, n, kk);

    int bn_grid = (n * (COUT / 4) + 255) / 256;
    if (bn_grid > 1184) bn_grid = 1184;
    bn_relu_kernel<<<bn_grid, 256>>>(out, gamma, beta, n);
}

// round 8
// speedup vs baseline: 3.0854x; 1.1427x over previous
#include <cuda_runtime.h>
#include <cstdint>

// ---------------------------------------------------------------------------
// BasicConvolutionBlock: sparse conv (gather-GEMM, K=27, Cin=Cout=64) + BN + ReLU
// Legacy mma.sync tf32 (compute_100-safe). 4 warps x 32-row tiles per CTA to
// halve the per-k full-B smem re-read (crossbar-bound per R7 model).
//   d_in[0] feats [N,64] f32      d_in[1] W [27,64,64] f32
//   d_in[2] gamma [64]            d_in[3] beta [64]
//   d_in[4] nbr_idx [27,N] i32    d_in[5] mask [27,N] i32
// out: [N,64] f32
// ---------------------------------------------------------------------------

#define CIN   64
#define COUT  64
#define MAXK  27
#define M_TILE 128
#define CTA   128
#define BN_EPS 1e-5f

// dynamic smem: A double-buffer (2 x 32KB) + WT double-buffer (2 x 16KB)
#define A_OFF0 0u
#define A_OFF1 32768u
#define B_OFF0 65536u
#define B_OFF1 81920u
#define SMEM_BYTES 98304

__device__ float g_stats[128];              // [0:64) sum, [64:128) sumsq
__device__ float g_wt[MAXK * CIN * COUT];   // tf32-rounded W, transposed [k][cout][cin]

// ---------------- helpers ---------------------------------------------------
__device__ __forceinline__ float to_tf32(float x) {
    uint32_t r;
    asm("cvt.rna.tf32.f32 %0, %1;" : "=r"(r) : "f"(x));
    return __uint_as_float(r);
}

__device__ __forceinline__ uint32_t smem_u32(const void* p) {
    uint32_t a;
    asm("{ .reg .u64 t; cvta.to.shared.u64 t, %1; cvt.u32.u64 %0, t; }"
        : "=r"(a) : "l"(p));
    return a;
}

__device__ __forceinline__ void cpa16(uint32_t dst, const void* src, uint32_t sz) {
    asm volatile("cp.async.cg.shared.global [%0], [%1], 16, %2;"
                 :: "r"(dst), "l"(src), "r"(sz) : "memory");
}
#define CP_COMMIT() asm volatile("cp.async.commit_group;" ::: "memory")
#define CP_WAIT0()  asm volatile("cp.async.wait_group 0;" ::: "memory")

// swizzled float4 index inside a [rows][64-float] tile
__device__ __forceinline__ uint32_t swz4(int r, int q) {
    return (uint32_t)(r * 16 + (q ^ (r & 7)));
}

// ---------------------------------------------------------------------------
__global__ void zero_stats_kernel() {
    int t = threadIdx.x;
    if (t < 128) g_stats[t] = 0.0f;
}

__global__ void prep_w_kernel(const float* __restrict__ w) {
    int k = blockIdx.x;
    const float* ws = w + (size_t)k * CIN * COUT;
    float* wd = g_wt + (size_t)k * CIN * COUT;
    for (int e = threadIdx.x; e < CIN * COUT; e += blockDim.x) {
        int ci = e >> 6, co = e & 63;
        wd[co * 64 + ci] = to_tf32(ws[e]);   // transpose: [cout][cin]
    }
}

// ---------------------------------------------------------------------------
// Conv kernel: CTA = 128 thr (4 warps), tile = 128 rows. Warp w owns rows
// [w*32, w*32+32) as two m16 sub-tiles. k-offsets accumulated in registers.
// ---------------------------------------------------------------------------
__global__ void __launch_bounds__(CTA, 2)
conv_kernel(const float* __restrict__ feats,
            const int* __restrict__ nbr,
            const int* __restrict__ mask,
            float*     __restrict__ out,
            int n, int kk) {
    extern __shared__ char smem[];
    __shared__ float sst[128];
    const uint32_t sb = smem_u32(smem);

    const int tid  = threadIdx.x;
    const int warp = tid >> 5, lane = tid & 31;
    const int lr = lane >> 2, le = lane & 3;
    const int cb = blockIdx.x * M_TILE;

    if (tid < 128) sst[tid] = 0.0f;

    const int grow = cb + tid;     // one gather row per thread

    const uint32_t a_off[2] = {A_OFF0, A_OFF1};
    const uint32_t b_off[2] = {B_OFF0, B_OFF1};

    // --- idx/mask prefetch (depth 2) + stage 0 issue -------------------------
    int pn; uint32_t pv;
    if (grow < n) { pv = (uint32_t)mask[grow]; pn = nbr[grow]; }
    else          { pv = 0; pn = 0; }

    {
        const char* src = (const char*)(feats + (size_t)pn * CIN);
        uint32_t abase = sb + a_off[0];
        uint32_t sz = pv ? 16u : 0u;
#pragma unroll
        for (int j = 0; j < 16; ++j)
            cpa16(abase + (swz4(tid, j) << 4), src + j * 16, sz);
        const char* wsrc = (const char*)g_wt;
        uint32_t bbase = sb + b_off[0];
#pragma unroll
        for (int j = 0; j < 8; ++j) {
            int e4 = tid + j * CTA;
            cpa16(bbase + (swz4(e4 >> 4, e4 & 15) << 4), wsrc + e4 * 16, 16u);
        }
        CP_COMMIT();
    }

    if (kk > 1) {
        if (grow < n) { int o = n + grow; pv = (uint32_t)mask[o]; pn = nbr[o]; }
        else          { pv = 0; pn = 0; }
    }

    float acc[8][2][4];            // [nt][row-subtile][frag]
#pragma unroll
    for (int nt = 0; nt < 8; ++nt)
#pragma unroll
        for (int t = 0; t < 2; ++t)
#pragma unroll
            for (int j = 0; j < 4; ++j) acc[nt][t][j] = 0.0f;

    const int ra = warp * 32 + lr; // subtile0 fragment row; subtile1 = +16

    for (int k = 0; k < kk; ++k) {
        CP_WAIT0();
        __syncthreads();

        // issue stage k+1 using prefetched idx/mask
        if (k + 1 < kk) {
            const int buf = (k + 1) & 1;
            const char* src = (const char*)(feats + (size_t)pn * CIN);
            uint32_t abase = sb + a_off[buf];
            uint32_t sz = pv ? 16u : 0u;
#pragma unroll
            for (int j = 0; j < 16; ++j)
                cpa16(abase + (swz4(tid, j) << 4), src + j * 16, sz);
            const char* wsrc = (const char*)(g_wt + (size_t)(k + 1) * CIN * COUT);
            uint32_t bbase = sb + b_off[buf];
#pragma unroll
            for (int j = 0; j < 8; ++j) {
                int e4 = tid + j * CTA;
                cpa16(bbase + (swz4(e4 >> 4, e4 & 15) << 4), wsrc + e4 * 16, 16u);
            }
            CP_COMMIT();
        }
        // prefetch idx/mask for stage k+2
        if (k + 2 < kk) {
            if (grow < n) { int o = (k + 2) * n + grow; pv = (uint32_t)mask[o]; pn = nbr[o]; }
            else          { pv = 0; pn = 0; }
        }

        // ---- compute from buffer k&1 ----
        const char* Ap = smem + a_off[k & 1];
        const char* Bp = smem + b_off[k & 1];
#pragma unroll
        for (int ks = 0; ks < 8; ++ks) {
            const uint32_t bq = (uint32_t)((((2 * ks) ^ lr) << 4) + (le << 2));
            const uint32_t a0o = (uint32_t)(ra << 8) + bq;    // subtile0
            uint32_t a0 = *(const uint32_t*)(Ap + a0o);
            uint32_t a1 = *(const uint32_t*)(Ap + a0o + 2048);
            uint32_t a2 = *(const uint32_t*)(Ap + (a0o ^ 16));
            uint32_t a3 = *(const uint32_t*)(Ap + ((a0o + 2048) ^ 16));
            const uint32_t a4o = a0o + 4096;                  // subtile1 (+16 rows)
            uint32_t a4 = *(const uint32_t*)(Ap + a4o);
            uint32_t a5 = *(const uint32_t*)(Ap + a4o + 2048);
            uint32_t a6 = *(const uint32_t*)(Ap + (a4o ^ 16));
            uint32_t a7 = *(const uint32_t*)(Ap + ((a4o + 2048) ^ 16));
#pragma unroll
            for (int nt = 0; nt < 8; ++nt) {
                const uint32_t b0o = (uint32_t)((nt * 8 + lr) << 8) + bq;
                uint32_t b0 = *(const uint32_t*)(Bp + b0o);
                uint32_t b1 = *(const uint32_t*)(Bp + (b0o ^ 16));
                asm volatile(
                    "mma.sync.aligned.m16n8k8.row.col.f32.tf32.tf32.f32 "
                    "{%0,%1,%2,%3}, {%4,%5,%6,%7}, {%8,%9}, {%0,%1,%2,%3};"
                    : "+f"(acc[nt][0][0]), "+f"(acc[nt][0][1]),
                      "+f"(acc[nt][0][2]), "+f"(acc[nt][0][3])
                    : "r"(a0), "r"(a1), "r"(a2), "r"(a3), "r"(b0), "r"(b1));
                asm volatile(
                    "mma.sync.aligned.m16n8k8.row.col.f32.tf32.tf32.f32 "
                    "{%0,%1,%2,%3}, {%4,%5,%6,%7}, {%8,%9}, {%0,%1,%2,%3};"
                    : "+f"(acc[nt][1][0]), "+f"(acc[nt][1][1]),
                      "+f"(acc[nt][1][2]), "+f"(acc[nt][1][3])
                    : "r"(a4), "r"(a5), "r"(a6), "r"(a7), "r"(b0), "r"(b1));
            }
        }
    }

    // ---- BN partial stats from register fragments (invalid rows hold 0) ----
#pragma unroll
    for (int nt = 0; nt < 8; ++nt) {
        float s0 = 0.f, q0 = 0.f, s1 = 0.f, q1 = 0.f;
#pragma unroll
        for (int t = 0; t < 2; ++t) {
            s0 += acc[nt][t][0] + acc[nt][t][2];
            q0 += acc[nt][t][0] * acc[nt][t][0] + acc[nt][t][2] * acc[nt][t][2];
            s1 += acc[nt][t][1] + acc[nt][t][3];
            q1 += acc[nt][t][1] * acc[nt][t][1] + acc[nt][t][3] * acc[nt][t][3];
        }
#pragma unroll
        for (int d = 4; d <= 16; d <<= 1) {
            s0 += __shfl_xor_sync(0xffffffffu, s0, d);
            q0 += __shfl_xor_sync(0xffffffffu, q0, d);
            s1 += __shfl_xor_sync(0xffffffffu, s1, d);
            q1 += __shfl_xor_sync(0xffffffffu, q1, d);
        }
        if (lane < 4) {
            int c0 = nt * 8 + lane * 2;
            atomicAdd(&sst[c0], s0);      atomicAdd(&sst[64 + c0], q0);
            atomicAdd(&sst[c0 + 1], s1);  atomicAdd(&sst[64 + c0 + 1], q1);
        }
    }

    // ---- fragments -> smem (swizzled) -> coalesced global write ----
    __syncthreads();
    {
        char* Sp = smem;   // reuse buffer A0
#pragma unroll
        for (int nt = 0; nt < 8; ++nt) {
            int col = nt * 8 + le * 2;
            int q = col >> 2, e = col & 3;
#pragma unroll
            for (int t = 0; t < 2; ++t) {
                int row = warp * 32 + t * 16 + lr;
                uint32_t o0 = (swz4(row, q) << 4) + (uint32_t)(e * 4);
                *(float2*)(Sp + o0)        = make_float2(acc[nt][t][0], acc[nt][t][1]);
                *(float2*)(Sp + o0 + 2048) = make_float2(acc[nt][t][2], acc[nt][t][3]);
            }
        }
    }
    __syncthreads();
    {
        const char* Sp = smem;
#pragma unroll
        for (int it = 0; it < 16; ++it) {
            int rl = (tid >> 4) + it * 8;
            int q = tid & 15;
            float4 v = *(const float4*)(Sp + (swz4(rl, q) << 4));
            int gr = cb + rl;
            if (gr < n) ((float4*)out)[(size_t)gr * 16 + q] = v;
        }
    }
    if (tid < 128) atomicAdd(&g_stats[tid], sst[tid]);
}

// ---------------------------------------------------------------------------
__global__ void bn_relu_kernel(float* __restrict__ out,
                               const float* __restrict__ gamma,
                               const float* __restrict__ beta,
                               int n) {
    __shared__ float sc[COUT], bi[COUT];
    const int tid = threadIdx.x;
    if (tid < COUT) {
        float inv_n = 1.0f / (float)n;
        float mean = g_stats[tid] * inv_n;
        float var = fmaxf(g_stats[64 + tid] * inv_n - mean * mean, 0.0f);
        float inv = rsqrtf(var + BN_EPS);
        float scl = gamma[tid] * inv;
        sc[tid] = scl;
        bi[tid] = beta[tid] - mean * scl;
    }
    __syncthreads();

    const int total = n * (COUT / 4);
    float4* o4 = (float4*)out;
    for (int i = blockIdx.x * blockDim.x + tid; i < total;
         i += gridDim.x * blockDim.x) {
        float4 v = o4[i];
        int c = (i & 15) << 2;
        v.x = fmaxf(fmaf(v.x, sc[c],     bi[c]),     0.f);
        v.y = fmaxf(fmaf(v.y, sc[c + 1], bi[c + 1]), 0.f);
        v.z = fmaxf(fmaf(v.z, sc[c + 2], bi[c + 2]), 0.f);
        v.w = fmaxf(fmaf(v.w, sc[c + 3], bi[c + 3]), 0.f);
        o4[i] = v;
    }
}

// ---------------------------------------------------------------------------
extern "C" void kernel_launch(void* const* d_in, const int* in_sizes, int n_in,
                              void* d_out, int out_size) {
    const float* feats = (const float*)d_in[0];
    const float* Wg    = (const float*)d_in[1];
    const float* gamma = (const float*)d_in[2];
    const float* beta  = (const float*)d_in[3];
    const int*   nbr   = (const int*)d_in[4];
    const int*   mask  = (const int*)d_in[5];
    float* out = (float*)d_out;

    const int n  = in_sizes[0] / CIN;              // 200000
    const int kk = in_sizes[1] / (CIN * COUT);     // 27

    cudaFuncSetAttribute(conv_kernel,
                         cudaFuncAttributeMaxDynamicSharedMemorySize,
                         SMEM_BYTES);

    zero_stats_kernel<<<1, 128>>>();
    prep_w_kernel<<<kk, 256>>>(Wg);

    const int grid = (n + M_TILE - 1) / M_TILE;    // 1563
    conv_kernel<<<grid, CTA, SMEM_BYTES>>>(feats, nbr, mask, out, n, kk);

    int bn_grid = (n * (COUT / 4) + 255) / 256;
    if (bn_grid > 1184) bn_grid = 1184;
    bn_relu_kernel<<<bn_grid, 256>>>(out, gamma, beta, n);
}